// round 7
// baseline (speedup 1.0000x reference)
#include <cuda_runtime.h>
#include <cstdint>

#define KDIM 64
#define MDIM 16
#define TPB  256
#define NPAIR 4                 // warp pairs per block
#define RPW  64                 // rows per pair-slab (2 per lane)
#define RPB  (NPAIR * RPW)      // 256 rows per block
#define KC   16                 // k-chunk per pipeline stage
#define NCH  (KDIM / KC)        // 4 chunks
#define TSTRIDE 20              // floats per tile row (16 data + 4 pad)
#define SLICE (RPW * TSTRIDE)   // floats per pair-buffer

typedef unsigned long long u64;
typedef unsigned int u32;

__device__ __forceinline__ u64 pack2(float lo, float hi) {
    u64 r;
    asm("mov.b64 %0, {%1, %2};" : "=l"(r) : "f"(lo), "f"(hi));
    return r;
}

__device__ __forceinline__ void unpack2(u64 v, float& lo, float& hi) {
    asm("mov.b64 {%0, %1}, %2;" : "=f"(lo), "=f"(hi) : "l"(v));
}

__device__ __forceinline__ u64 fma2(u64 a, u64 b, u64 c) {
    u64 d;
    asm("fma.rn.f32x2 %0, %1, %2, %3;" : "=l"(d) : "l"(a), "l"(b), "l"(c));
    return d;
}

__device__ __forceinline__ void cp16(u32 smem_dst, const void* gsrc) {
    asm volatile("cp.async.cg.shared.global [%0], [%1], 16;\n"
                 :: "r"(smem_dst), "l"(gsrc));
}
__device__ __forceinline__ void cp_commit() {
    asm volatile("cp.async.commit_group;\n");
}
template <int N>
__device__ __forceinline__ void cp_wait() {
    asm volatile("cp.async.wait_group %0;\n" :: "n"(N));
}
__device__ __forceinline__ void pair_bar(int id) {
    asm volatile("bar.sync %0, 64;" :: "r"(id) : "memory");
}

__global__ __launch_bounds__(TPB, 4)
void dual_compress_kernel(const float* __restrict__ phi_fwd,
                          const float* __restrict__ phi_bwd,
                          const float* __restrict__ alpha_fwd,
                          const float* __restrict__ alpha_bwd,
                          float* __restrict__ out,
                          int V)
{
    // Per-pair double-buffered tiles: 4 pairs x 2 bufs x 64 rows x 20 floats = 40,960 B
    __shared__ float tile[NPAIR][2][SLICE];
    __shared__ ulonglong2 sw2[KDIM * 4];      // 4,096 B weight table (8 m-pairs per k)
    u64* swf = (u64*)sw2;

    const int side = blockIdx.y;
    const float* __restrict__ phi   = side ? phi_bwd   : phi_fwd;
    const float* __restrict__ alpha = side ? alpha_bwd : alpha_fwd;
    float* __restrict__ y = out + (size_t)side * (size_t)V * MDIM;

    const int tid  = threadIdx.x;
    const int w    = tid >> 5;
    const int lane = tid & 31;
    const int p    = w & 3;          // pair id (tile owner)
    const int h    = w >> 2;         // m-half: 0 -> m[0:8), 1 -> m[8:16)
    const int wtid = lane + 32 * h;  // 0..63 within the pair

    const int blockRow = blockIdx.x * RPB;
    const int slab     = blockRow + p * RPW;

    u32 tb0 = (u32)__cvta_generic_to_shared(&tile[p][0][0]);
    u32 tb1 = (u32)__cvta_generic_to_shared(&tile[p][1][0]);

    // ---- prologue: both warps of the pair stage chunks 0 and 1 of their slab
    // 64 rows x 16 floats = 256 float4 per chunk; 64 threads -> 4 each.
#pragma unroll
    for (int buf = 0; buf < 2; ++buf) {
        const int ch = buf;
        const u32 tb = buf ? tb1 : tb0;
#pragma unroll
        for (int i = 0; i < 4; ++i) {
            int idx  = wtid + i * 64;
            int row  = idx >> 2;                    // 0..63
            int c4   = idx & 3;
            int grow = min(slab + row, V - 1);
            cp16(tb + (u32)(row * TSTRIDE + c4 * 4) * 4u,
                 phi + (size_t)grow * KDIM + ch * KC + c4 * 4);
        }
        cp_commit();
    }

    // ---- shared weight table: swf[k*8 + mp] = {exp(alpha[2mp][k]), exp(alpha[2mp+1][k])}
#pragma unroll
    for (int t = 0; t < 2; ++t) {
        int idx = tid + t * TPB;                    // 512 entries
        int k  = idx >> 3;
        int mp = idx & 7;
        float w0 = __expf(alpha[(2 * mp)     * KDIM + k]);
        float w1 = __expf(alpha[(2 * mp + 1) * KDIM + k]);
        swf[idx] = pack2(w0, w1);
    }
    __syncthreads();   // weights visible to all

    const int r0 = slab + lane;
    const int r1 = slab + lane + 32;

    // 2 rows x 4 m-pairs (this half's 8 m-values)
    u64 acc0[4], acc1[4];
#pragma unroll
    for (int q = 0; q < 4; ++q) { acc0[q] = 0ull; acc1[q] = 0ull; }

#pragma unroll
    for (int ch = 0; ch < NCH; ++ch) {
        if (ch == NCH - 1) cp_wait<0>(); else cp_wait<1>();
        pair_bar(1 + p);   // both warps' cp groups for this chunk complete

        const int buf = ch & 1;
        const float4* __restrict__ t0 = (const float4*)&tile[p][buf][lane * TSTRIDE];
        const float4* __restrict__ t1 = (const float4*)&tile[p][buf][(lane + 32) * TSTRIDE];

#pragma unroll
        for (int j4 = 0; j4 < KC / 4; ++j4) {
            float4 a0 = t0[j4];
            float4 a1 = t1[j4];

            float e0[4], e1[4];
            e0[0] = __expf(a0.x); e0[1] = __expf(a0.y); e0[2] = __expf(a0.z); e0[3] = __expf(a0.w);
            e1[0] = __expf(a1.x); e1[1] = __expf(a1.y); e1[2] = __expf(a1.z); e1[3] = __expf(a1.w);

            const int kbase = ch * KC + j4 * 4;
#pragma unroll
            for (int j = 0; j < 4; ++j) {
                const int k = kbase + j;
                u64 E0 = pack2(e0[j], e0[j]);
                u64 E1 = pack2(e1[j], e1[j]);

                // this half's 4 m-pairs: entries [k*8 + 4h .. +4) = 2x ulonglong2
                ulonglong2 wA = sw2[k * 4 + 2 * h + 0];
                ulonglong2 wB = sw2[k * 4 + 2 * h + 1];

                acc0[0] = fma2(E0, wA.x, acc0[0]);
                acc1[0] = fma2(E1, wA.x, acc1[0]);
                acc0[1] = fma2(E0, wA.y, acc0[1]);
                acc1[1] = fma2(E1, wA.y, acc1[1]);
                acc0[2] = fma2(E0, wB.x, acc0[2]);
                acc1[2] = fma2(E1, wB.x, acc1[2]);
                acc0[3] = fma2(E0, wB.y, acc0[3]);
                acc1[3] = fma2(E1, wB.y, acc1[3]);
            }
        }

        // restage this pair's consumed buffer with chunk ch+2
        if (ch + 2 < NCH) {
            pair_bar(1 + p);   // both warps done reading tile[p][buf]
            const int nch = ch + 2;
            const u32 tb = buf ? tb1 : tb0;
#pragma unroll
            for (int i = 0; i < 4; ++i) {
                int idx  = wtid + i * 64;
                int row  = idx >> 2;
                int c4   = idx & 3;
                int grow = min(slab + row, V - 1);
                cp16(tb + (u32)(row * TSTRIDE + c4 * 4) * 4u,
                     phi + (size_t)grow * KDIM + nch * KC + c4 * 4);
            }
            cp_commit();
        }
    }

    // ---- epilogue: y = log(sum); this half writes m [8h, 8h+8) of each row
    float y0[8], y1[8];
#pragma unroll
    for (int q = 0; q < 4; ++q) {
        float s0a, s0b, s1a, s1b;
        unpack2(acc0[q], s0a, s0b);
        unpack2(acc1[q], s1a, s1b);
        y0[2 * q] = __logf(s0a); y0[2 * q + 1] = __logf(s0b);
        y1[2 * q] = __logf(s1a); y1[2 * q + 1] = __logf(s1b);
    }

    if (r0 < V) {
        float4* o = (float4*)(y + (size_t)r0 * MDIM + 8 * h);
        o[0] = make_float4(y0[0], y0[1], y0[2], y0[3]);
        o[1] = make_float4(y0[4], y0[5], y0[6], y0[7]);
    }
    if (r1 < V) {
        float4* o = (float4*)(y + (size_t)r1 * MDIM + 8 * h);
        o[0] = make_float4(y1[0], y1[1], y1[2], y1[3]);
        o[1] = make_float4(y1[4], y1[5], y1[6], y1[7]);
    }
}

extern "C" void kernel_launch(void* const* d_in, const int* in_sizes, int n_in,
                              void* d_out, int out_size)
{
    const float* d_out_t   = (const float*)d_in[0];  // (V, 64) fwd phi
    const float* d_in_t    = (const float*)d_in[1];  // (V, 64) bwd phi
    const float* alpha_fwd = (const float*)d_in[2];  // (16, 64)
    const float* alpha_bwd = (const float*)d_in[3];  // (16, 64)
    float* out = (float*)d_out;                      // [y_fwd (V,16) | y_bwd (V,16)]

    const int V = in_sizes[0] / KDIM;

    dim3 grid((V + RPB - 1) / RPB, 2);
    dual_compress_kernel<<<grid, TPB>>>(d_out_t, d_in_t, alpha_fwd, alpha_bwd, out, V);
}